// round 2
// baseline (speedup 1.0000x reference)
#include <cuda_runtime.h>
#include <cstdint>
#include <cstddef>

// RNN_49297634623576: out = fc_w @ tanh(w_ih @ x[:,27,:] + b_ih + b_hh) + fc_b
// hx == 0 => w_hh unused.
//
// R2 change vs R1: RPT 4 -> 2 (grid 128 -> 256 CTAs, warps 512 -> 1024).
// R1 had fewer warps than SMSPs (512 < 592) -> latency-bound at occ=6.1%,
// issue=27%. Doubling resident warps (and 2 CTAs/SM) hides LDS/MUFU latency.
// Also: cheaper 5-issue tanh via ex2.approx + rcp.approx fused form.

#define NB   65536
#define NIN  28
#define NHID 64
#define NOUT 10
#define RPT  2      // batch rows per thread
#define TPB  128    // 256 rows/block -> 256 blocks

typedef unsigned long long u64;

__device__ __forceinline__ u64 pk2(float a, float b) {
    u64 r; asm("mov.b64 %0,{%1,%2};" : "=l"(r) : "f"(a), "f"(b)); return r;
}
__device__ __forceinline__ void upk2(u64 v, float& a, float& b) {
    asm("mov.b64 {%0,%1},%2;" : "=f"(a), "=f"(b) : "l"(v));
}
__device__ __forceinline__ u64 ffma2(u64 a, u64 b, u64 c) {
    u64 d; asm("fma.rn.f32x2 %0,%1,%2,%3;" : "=l"(d) : "l"(a), "l"(b), "l"(c)); return d;
}
__device__ __forceinline__ float hsum2(u64 v) {
    float a, b; upk2(v, a, b); return a + b;
}

// tanh(x) = 1 - 2*rcp(exp(2x)+1); 5 issues: FMUL, MUFU.EX2, FADD, MUFU.RCP, FFMA.
__device__ __forceinline__ float tanh_fast(float x) {
    const float LOG2E_X2 = 2.8853900817779268f; // 2*log2(e)
    float e, r;
    asm("ex2.approx.ftz.f32 %0, %1;" : "=f"(e) : "f"(x * LOG2E_X2));
    asm("rcp.approx.ftz.f32 %0, %1;" : "=f"(r) : "f"(e + 1.0f));
    return fmaf(-2.0f, r, 1.0f);
}

__global__ void __launch_bounds__(TPB, 2)
rnn_fused_kernel(const float* __restrict__ x,
                 const float* __restrict__ w_ih,
                 const float* __restrict__ b_ih,
                 const float* __restrict__ b_hh,
                 const float* __restrict__ fc_w,
                 const float* __restrict__ fc_b,
                 float* __restrict__ out)
{
    __shared__ u64   s_w[NHID][NIN / 2];   // {w[j][2p], w[j][2p+1]}
    __shared__ float s_b[NHID];            // b_ih + b_hh
    __shared__ u64   s_fc[NOUT][NHID];     // {fc_w[k][j], fc_w[k][j]} duplicated
    __shared__ float s_fcb[NOUT];

    const int tid = threadIdx.x;

    for (int i = tid; i < NHID * (NIN / 2); i += TPB) {
        int j = i / (NIN / 2), p = i % (NIN / 2);
        s_w[j][p] = pk2(w_ih[j * NIN + 2 * p], w_ih[j * NIN + 2 * p + 1]);
    }
    for (int i = tid; i < NHID; i += TPB) s_b[i] = b_ih[i] + b_hh[i];
    for (int i = tid; i < NOUT * NHID; i += TPB) {
        float w = fc_w[i];
        s_fc[i / NHID][i % NHID] = pk2(w, w);
    }
    if (tid < NOUT) s_fcb[tid] = fc_b[tid];
    __syncthreads();

    const long long base = ((long long)blockIdx.x * TPB + tid) * RPT;

    // Last input row (28 floats) for RPT batch rows; offset 756 floats is 16B aligned.
    u64 in[RPT][NIN / 2];
#pragma unroll
    for (int r = 0; r < RPT; r++) {
        const float4* p = reinterpret_cast<const float4*>(x + (size_t)(base + r) * 784 + 756);
#pragma unroll
        for (int q = 0; q < 7; q++) {
            float4 v = p[q];
            in[r][2 * q]     = pk2(v.x, v.y);
            in[r][2 * q + 1] = pk2(v.z, v.w);
        }
    }

    // FC accumulators: oa[k] = {row0, row1}
    u64 oa[NOUT];
#pragma unroll
    for (int k = 0; k < NOUT; k++) oa[k] = 0ull;

#pragma unroll 4
    for (int j = 0; j < NHID; j++) {
        u64 a0 = 0ull, a1 = 0ull;
#pragma unroll
        for (int p = 0; p < NIN / 2; p++) {
            u64 w = s_w[j][p];               // warp-uniform LDS.64 broadcast
            a0 = ffma2(w, in[0][p], a0);
            a1 = ffma2(w, in[1][p], a1);
        }
        const float bj = s_b[j];
        float h0 = tanh_fast(hsum2(a0) + bj);
        float h1 = tanh_fast(hsum2(a1) + bj);
        u64 hp = pk2(h0, h1);
#pragma unroll
        for (int k = 0; k < NOUT; k++) {
            oa[k] = ffma2(s_fc[k][j], hp, oa[k]); // {w,w} * {h0,h1}
        }
    }

    // Epilogue: add fc_b, store 10 floats per row as 5x STG.64 (rows 8B aligned).
    float res[RPT][NOUT];
#pragma unroll
    for (int k = 0; k < NOUT; k++) {
        float fb = s_fcb[k];
        float v0, v1;
        upk2(oa[k], v0, v1);
        res[0][k] = v0 + fb;
        res[1][k] = v1 + fb;
    }
#pragma unroll
    for (int r = 0; r < RPT; r++) {
        float2* o2 = reinterpret_cast<float2*>(out + (size_t)(base + r) * NOUT);
#pragma unroll
        for (int k = 0; k < NOUT / 2; k++) {
            o2[k] = make_float2(res[r][2 * k], res[r][2 * k + 1]);
        }
    }
}

extern "C" void kernel_launch(void* const* d_in, const int* in_sizes, int n_in,
                              void* d_out, int out_size)
{
    (void)in_sizes; (void)n_in; (void)out_size;
    const float* x    = (const float*)d_in[0];
    const float* w_ih = (const float*)d_in[1];
    // d_in[2] = w_hh : unused (hx == 0)
    const float* b_ih = (const float*)d_in[3];
    const float* b_hh = (const float*)d_in[4];
    const float* fc_w = (const float*)d_in[5];
    const float* fc_b = (const float*)d_in[6];
    float* out = (float*)d_out;

    const int rows_per_block = TPB * RPT;          // 256
    const int blocks = NB / rows_per_block;        // 256, exact

    rnn_fused_kernel<<<blocks, TPB>>>(x, w_ih, b_ih, b_hh, fc_w, fc_b, out);
}